// round 14
// baseline (speedup 1.0000x reference)
#include <cuda_runtime.h>
#include <cuda_bf16.h>
#include <cstdint>
#include <cstddef>

#define H      16
#define BSZ    4
#define SEQ    2048
#define DIM    1024
#define DH     64
#define MROWS  (BSZ * SEQ)   // 8192
#define QSCALE 0.1803368801111244f   // 0.125 * log2(e)
#define NWORDS (BSZ * SEQ * H * (SEQ / 32))   // 8388608 packed mask words

// ---- scratch (module-scope, no runtime allocation) -------------------------
__device__ __nv_bfloat16 g_wh[4][DIM * DIM];      // W^T hi  [n][k]
__device__ __nv_bfloat16 g_wl[4][DIM * DIM];      // W^T lo
__device__ __nv_bfloat16 g_qh[BSZ * H * SEQ * DH], g_ql[BSZ * H * SEQ * DH];
__device__ __nv_bfloat16 g_kh[BSZ * H * SEQ * DH], g_kl[BSZ * H * SEQ * DH];
__device__ __nv_bfloat16 g_vth[BSZ * H * DH * SEQ], g_vtl[BSZ * H * DH * SEQ]; // V^T [B,H,DH,S]
__device__ __nv_bfloat16 g_oh[MROWS * DIM], g_ol[MROWS * DIM];                 // attn out
__device__ uint32_t g_pmask[NWORDS];              // packed mask (33.5 MB)

// ---- dataflow flags (zeroed inside transpose kernel each replay) ------------
__device__ int g_cntP[3][8][BSZ];   // [z=Q/K/V][ntile][b] -> reaches 16
__device__ int g_cntA[BSZ][16];     // [b][qtile]          -> reaches 16
__device__ int g_cntM;              // pack CTAs done      -> reaches 512

// ============================================================================
// PTX helpers
// ============================================================================
__device__ __forceinline__ uint32_t smem_u32(const void* p) {
    uint32_t a;
    asm("{ .reg .u64 t; cvta.to.shared.u64 t, %1; cvt.u32.u64 %0, t; }"
        : "=r"(a) : "l"(p));
    return a;
}

#define CP_ASYNC16(dst, src) \
    asm volatile("cp.async.cg.shared.global [%0], [%1], 16;" \
                 :: "r"(dst), "l"(src) : "memory")
#define CP_COMMIT() asm volatile("cp.async.commit_group;" ::: "memory")
#define CP_WAIT(n)  asm volatile("cp.async.wait_group %0;" :: "n"(n) : "memory")

#define LDM_X4(r0, r1, r2, r3, addr) \
    asm volatile("ldmatrix.sync.aligned.m8n8.x4.shared.b16 {%0,%1,%2,%3}, [%4];" \
                 : "=r"(r0), "=r"(r1), "=r"(r2), "=r"(r3) : "r"(addr))

#define MMA_BF16(d, a, b0, b1)                                                \
    asm volatile("mma.sync.aligned.m16n8k16.row.col.f32.bf16.bf16.f32 "       \
                 "{%0,%1,%2,%3}, {%4,%5,%6,%7}, {%8,%9}, {%0,%1,%2,%3};"      \
                 : "+f"((d)[0]), "+f"((d)[1]), "+f"((d)[2]), "+f"((d)[3])     \
                 : "r"((a)[0]), "r"((a)[1]), "r"((a)[2]), "r"((a)[3]),        \
                   "r"(b0), "r"(b1))

#define EX2F(d, s) asm("ex2.approx.f32 %0, %1;" : "=f"(d) : "f"(s))

// XOR-swizzled offset for 64B-row bf16 tiles (r = row, c16 = 16B column 0..3).
#define SWZ(r, c16) (((r) << 6) + ((((c16) ^ (((r) >> 1) & 3))) << 4))

__device__ __forceinline__ void split2(float2 v, uint32_t& hi, uint32_t& lo) {
    __nv_bfloat162 h;
    h.x = __float2bfloat16(v.x);
    h.y = __float2bfloat16(v.y);
    __nv_bfloat162 l;
    l.x = __float2bfloat16(v.x - __bfloat162float(h.x));
    l.y = __float2bfloat16(v.y - __bfloat162float(h.y));
    hi = *(uint32_t*)&h;
    lo = *(uint32_t*)&l;
}

// ============================================================================
// Prologue: weight transpose+split (z = 4 weights); block (0,0,0) also zeroes
// the dataflow flags (kernel completes before mega_kernel starts).
// ============================================================================
struct TArg { const float* W[4]; __nv_bfloat16* Th[4]; __nv_bfloat16* Tl[4]; };

__global__ void __launch_bounds__(256)
transpose_split_kernel(TArg p)
{
    __shared__ float t[32][33];
    const int z = blockIdx.z;
    if (z == 0 && blockIdx.x == 0 && blockIdx.y == 0) {
        const int tid = threadIdx.y * 32 + threadIdx.x;
        if (tid < 3 * 8 * BSZ) ((int*)g_cntP)[tid] = 0;
        if (tid < BSZ * 16)    ((int*)g_cntA)[tid] = 0;
        if (tid == 0)          g_cntM = 0;
    }
    const float* W = p.W[z];
    __nv_bfloat16* Th = p.Th[z];
    __nv_bfloat16* Tl = p.Tl[z];
    const int tx = threadIdx.x, ty = threadIdx.y;       // 32 x 8
    const int nb = blockIdx.x * 32, kb = blockIdx.y * 32;
    #pragma unroll
    for (int i = 0; i < 4; i++)
        t[ty + i * 8][tx] = W[(size_t)(kb + ty + i * 8) * DIM + nb + tx];
    __syncthreads();
    #pragma unroll
    for (int i = 0; i < 4; i++) {
        const float v = t[tx][ty + i * 8];
        const __nv_bfloat16 h = __float2bfloat16(v);
        Th[(size_t)(nb + ty + i * 8) * DIM + kb + tx] = h;
        Tl[(size_t)(nb + ty + i * 8) * DIM + kb + tx] =
            __float2bfloat16(v - __bfloat162float(h));
    }
}

// ============================================================================
// GEMM body (unchanged from R13). 3-stage cp.async, XOR-swizzled bf16 tiles.
// ============================================================================
#define GSTRIDE    36864
#define MEGA_SMEM  110592

struct GArg {
    const float* Af;
    const __nv_bfloat16 *Ah, *Al;
    const __nv_bfloat16 *Wh, *Wl;
    const float* bias;
    float* Cf;
    __nv_bfloat16 *Ch, *Cl;
    int omode;
    float scale;
};

template <int AFP32>
__device__ void gemm_body(const GArg& a, int bxx, int byy, char* smem)
{
    const uint32_t sb = smem_u32(smem);
    const int tid = threadIdx.x;
    const int wid = tid >> 5, lane = tid & 31;
    const int wm = wid & 3, wn = wid >> 2;
    const int m0 = byy * 128, n0 = bxx * 128;

    const int a_row  = lane & 15;
    const int a_c16  = (lane >> 4) & 1;
    const int b_nrow = (lane & 7) + ((lane >> 4) & 1) * 8;
    const int b_c16  = (lane >> 3) & 1;

    float acc[2][8][4];
    #pragma unroll
    for (int i = 0; i < 2; i++)
        #pragma unroll
        for (int j = 0; j < 8; j++)
            #pragma unroll
            for (int k = 0; k < 4; k++) acc[i][j][k] = 0.f;

    const int wOff = AFP32 ? 20480 : 16384;

    auto issue = [&](int it) {
        const int kc = it * 32;
        const uint32_t st = sb + (it % 3) * GSTRIDE;
        if (AFP32) {
            #pragma unroll
            for (int i = 0; i < 4; i++) {
                const int idx = tid + i * 256;
                const int r = idx >> 3, c = idx & 7;
                CP_ASYNC16(st + r * 160 + c * 16,
                           a.Af + (size_t)(m0 + r) * DIM + kc + c * 4);
            }
            #pragma unroll
            for (int i = 0; i < 2; i++) {
                const int idx = tid + i * 256;
                const int r = idx >> 2, c16 = idx & 3;
                const uint32_t o = SWZ(r, c16);
                const size_t gw = (size_t)(n0 + r) * DIM + kc + c16 * 8;
                CP_ASYNC16(st + 20480 + o, a.Wh + gw);
                CP_ASYNC16(st + 28672 + o, a.Wl + gw);
            }
        } else {
            #pragma unroll
            for (int i = 0; i < 2; i++) {
                const int idx = tid + i * 256;
                const int r = idx >> 2, c16 = idx & 3;
                const uint32_t o = SWZ(r, c16);
                const size_t ga = (size_t)(m0 + r) * DIM + kc + c16 * 8;
                const size_t gw = (size_t)(n0 + r) * DIM + kc + c16 * 8;
                CP_ASYNC16(st + o,         a.Ah + ga);
                CP_ASYNC16(st + 8192 + o,  a.Al + ga);
                CP_ASYNC16(st + 16384 + o, a.Wh + gw);
                CP_ASYNC16(st + 24576 + o, a.Wl + gw);
            }
        }
        CP_COMMIT();
    };

    issue(0);
    issue(1);

    #pragma unroll 1
    for (int it = 0; it < 32; ++it) {
        if (it + 1 < 32) { CP_WAIT(1); } else { CP_WAIT(0); }
        __syncthreads();
        if (it + 2 < 32) issue(it + 2);

        const uint32_t st = sb + (it % 3) * GSTRIDE;
        const char* stc = smem + (it % 3) * GSTRIDE;

        #pragma unroll
        for (int ks = 0; ks < 2; ++ks) {
            uint32_t ah[2][4], al[2][4];
            if (AFP32) {
                const int cb = ks * 16 + (lane & 3) * 2;
                #pragma unroll
                for (int mt = 0; mt < 2; ++mt) {
                    const int r = wm * 32 + mt * 16 + (lane >> 2);
                    const char* base = stc + (size_t)r * 160 + cb * 4;
                    const float2 v00 = *(const float2*)(base);
                    const float2 v01 = *(const float2*)(base + 8 * 160);
                    const float2 v10 = *(const float2*)(base + 32);
                    const float2 v11 = *(const float2*)(base + 8 * 160 + 32);
                    split2(v00, ah[mt][0], al[mt][0]);
                    split2(v01, ah[mt][1], al[mt][1]);
                    split2(v10, ah[mt][2], al[mt][2]);
                    split2(v11, ah[mt][3], al[mt][3]);
                }
            } else {
                #pragma unroll
                for (int mt = 0; mt < 2; ++mt) {
                    const int ar = wm * 32 + mt * 16 + a_row;
                    const uint32_t ao = SWZ(ar, ks * 2 + a_c16);
                    LDM_X4(ah[mt][0], ah[mt][1], ah[mt][2], ah[mt][3], st + ao);
                    LDM_X4(al[mt][0], al[mt][1], al[mt][2], al[mt][3], st + 8192 + ao);
                }
            }
            uint32_t b[4][4];
            #pragma unroll
            for (int g = 0; g < 4; ++g) {
                const int br = wn * 64 + g * 16 + b_nrow;
                LDM_X4(b[g][0], b[g][1], b[g][2], b[g][3],
                       st + wOff + SWZ(br, ks * 2 + b_c16));
            }
            #pragma unroll
            for (int mt = 0; mt < 2; ++mt)
                #pragma unroll
                for (int nt = 0; nt < 8; ++nt) {
                    MMA_BF16(acc[mt][nt], ah[mt],
                             b[nt >> 1][(nt & 1) * 2], b[nt >> 1][(nt & 1) * 2 + 1]);
                    MMA_BF16(acc[mt][nt], al[mt],
                             b[nt >> 1][(nt & 1) * 2], b[nt >> 1][(nt & 1) * 2 + 1]);
                }
            #pragma unroll
            for (int g = 0; g < 4; ++g) {
                const int br = wn * 64 + g * 16 + b_nrow;
                LDM_X4(b[g][0], b[g][1], b[g][2], b[g][3],
                       st + wOff + 8192 + SWZ(br, ks * 2 + b_c16));
            }
            #pragma unroll
            for (int mt = 0; mt < 2; ++mt)
                #pragma unroll
                for (int nt = 0; nt < 8; ++nt)
                    MMA_BF16(acc[mt][nt], ah[mt],
                             b[nt >> 1][(nt & 1) * 2], b[nt >> 1][(nt & 1) * 2 + 1]);
        }
    }

    // ---- epilogue
    const int r0l = lane >> 2, c0 = (lane & 3) * 2;
    #pragma unroll
    for (int mt = 0; mt < 2; ++mt) {
        #pragma unroll
        for (int nt = 0; nt < 8; ++nt) {
            const int n = n0 + wn * 64 + nt * 8 + c0;
            const float bx = a.bias[n], by = a.bias[n + 1];
            #pragma unroll
            for (int half = 0; half < 2; ++half) {
                const int r = m0 + wm * 32 + mt * 16 + r0l + half * 8;
                const float vx = (acc[mt][nt][half * 2 + 0] + bx) * a.scale;
                const float vy = (acc[mt][nt][half * 2 + 1] + by) * a.scale;
                if (a.omode == 2) {
                    *(float2*)&a.Cf[(size_t)r * DIM + n] = make_float2(vx, vy);
                } else {
                    const int bb = r >> 11, s = r & (SEQ - 1);
                    const int hh = n >> 6, d = n & (DH - 1);
                    const __nv_bfloat16 hx = __float2bfloat16(vx);
                    const __nv_bfloat16 hy = __float2bfloat16(vy);
                    const __nv_bfloat16 lx = __float2bfloat16(vx - __bfloat162float(hx));
                    const __nv_bfloat16 ly = __float2bfloat16(vy - __bfloat162float(hy));
                    if (a.omode == 0) {
                        const size_t idx = ((size_t)(bb * H + hh) * SEQ + s) * DH + d;
                        __nv_bfloat162 hv; hv.x = hx; hv.y = hy;
                        __nv_bfloat162 lv; lv.x = lx; lv.y = ly;
                        *(__nv_bfloat162*)(a.Ch + idx) = hv;
                        *(__nv_bfloat162*)(a.Cl + idx) = lv;
                    } else {
                        const size_t base = (size_t)(bb * H + hh) * DH;
                        a.Ch[(base + d) * SEQ + s]     = hx;
                        a.Ch[(base + d + 1) * SEQ + s] = hy;
                        a.Cl[(base + d) * SEQ + s]     = lx;
                        a.Cl[(base + d + 1) * SEQ + s] = ly;
                    }
                }
            }
        }
    }
}

// ============================================================================
// Attention body: packed-mask version. Per tile per thread: 2x LDG.64 packed
// words instead of 16x LDG.64 int32 (DRAM 1.07GB -> 33MB).
// ============================================================================
#define ATTN_QH   73728
#define ATTN_QL   92160

__device__ void attn_body(
        const __nv_bfloat16* __restrict__ qh, const __nv_bfloat16* __restrict__ ql,
        const __nv_bfloat16* __restrict__ kh, const __nv_bfloat16* __restrict__ kl,
        const __nv_bfloat16* __restrict__ vth, const __nv_bfloat16* __restrict__ vtl,
        __nv_bfloat16* __restrict__ oh, __nv_bfloat16* __restrict__ ol,
        int qt, int bh, char* smem)
{
    const uint32_t sb = smem_u32(smem);
    const int tid = threadIdx.x;
    const int wid = tid >> 5, lane = tid & 31;
    const int b = bh >> 4, h = bh & 15;
    const int q0 = qt * 128;
    const int wrow = wid * 16;

    const int a_row  = lane & 15;
    const int a_koff = ((lane >> 4) & 1) * 8;
    const int b_nrow = (lane & 7) + ((lane >> 4) & 1) * 8;
    const int b_koff = ((lane >> 3) & 1) * 8;
    const int r0 = lane >> 2, c2 = (lane & 3) * 2;

    #pragma unroll
    for (int i = 0; i < 8; i++) {
        const int idx = tid + i * 256;
        const int part = idx >> 10;
        const int id = idx & 1023;
        const int r = id >> 3, c = id & 7;
        const __nv_bfloat16* src = (part ? ql : qh)
            + ((size_t)bh * SEQ + q0 + r) * DH + c * 8;
        CP_ASYNC16(sb + (part ? ATTN_QL : ATTN_QH) + r * 144 + c * 16, src);
    }
    CP_COMMIT();

    float O[8][4];
    #pragma unroll
    for (int nt = 0; nt < 8; nt++)
        #pragma unroll
        for (int q = 0; q < 4; q++) O[nt][q] = 0.f;
    float lrun0 = 0.f, lrun1 = 0.f;

    const int row0 = q0 + wrow + r0;
    const uint32_t* pm0 = g_pmask + ((size_t)(b * SEQ + row0) * H + h) * 64;
    const uint32_t* pm1 = pm0 + (size_t)8 * H * 64;

    auto issue_kv = [&](int kt) {
        const int k0i = kt * 64;
        const uint32_t st = sb + (kt & 1) * 36864;
        #pragma unroll
        for (int i = 0; i < 8; i++) {
            const int idx = tid + i * 256;
            const int part = idx >> 9;
            const int id = idx & 511;
            const int r = id >> 3, c = id & 7;
            const __nv_bfloat16* src;
            if (part == 0)      src = kh  + ((size_t)bh * SEQ + k0i + r) * DH + c * 8;
            else if (part == 1) src = kl  + ((size_t)bh * SEQ + k0i + r) * DH + c * 8;
            else if (part == 2) src = vth + ((size_t)bh * DH + r) * SEQ + k0i + c * 8;
            else                src = vtl + ((size_t)bh * DH + r) * SEQ + k0i + c * 8;
            CP_ASYNC16(st + part * 9216 + r * 144 + c * 16, src);
        }
        CP_COMMIT();
    };

    issue_kv(0);

    #pragma unroll 1
    for (int kt = 0; kt < 32; ++kt) {
        const int k0 = kt * 64;
        CP_WAIT(0);
        __syncthreads();
        if (kt + 1 < 32) issue_kv(kt + 1);

        const uint32_t kbase = sb + (kt & 1) * 36864;
        const uint32_t qho = sb + ATTN_QH + (wrow + a_row) * 144 + a_koff * 2;
        const uint32_t qlo = sb + ATTN_QL + (wrow + a_row) * 144 + a_koff * 2;

        // packed mask words for this 64-kv tile (2 words per row)
        const uint2 mw0 = *(const uint2*)(pm0 + (k0 >> 5));
        const uint2 mw1 = *(const uint2*)(pm1 + (k0 >> 5));

        float S[8][4];
        #pragma unroll
        for (int nt = 0; nt < 8; nt++)
            #pragma unroll
            for (int q = 0; q < 4; q++) S[nt][q] = 0.f;

        #pragma unroll
        for (int ks = 0; ks < 4; ++ks) {
            uint32_t qhf[4], qlf[4];
            LDM_X4(qhf[0], qhf[1], qhf[2], qhf[3], qho + ks * 32);
            LDM_X4(qlf[0], qlf[1], qlf[2], qlf[3], qlo + ks * 32);
            uint32_t bf[4][4];
            #pragma unroll
            for (int g = 0; g < 4; ++g)
                LDM_X4(bf[g][0], bf[g][1], bf[g][2], bf[g][3],
                       kbase + (g * 16 + b_nrow) * 144 + (ks * 16 + b_koff) * 2);
            #pragma unroll
            for (int nt = 0; nt < 8; ++nt) {
                MMA_BF16(S[nt], qhf, bf[nt >> 1][(nt & 1) * 2], bf[nt >> 1][(nt & 1) * 2 + 1]);
                MMA_BF16(S[nt], qlf, bf[nt >> 1][(nt & 1) * 2], bf[nt >> 1][(nt & 1) * 2 + 1]);
            }
            #pragma unroll
            for (int g = 0; g < 4; ++g)
                LDM_X4(bf[g][0], bf[g][1], bf[g][2], bf[g][3],
                       kbase + 9216 + (g * 16 + b_nrow) * 144 + (ks * 16 + b_koff) * 2);
            #pragma unroll
            for (int nt = 0; nt < 8; ++nt)
                MMA_BF16(S[nt], qhf, bf[nt >> 1][(nt & 1) * 2], bf[nt >> 1][(nt & 1) * 2 + 1]);
        }

        const uint32_t vtb = kbase + 18432;
        #pragma unroll
        for (int ks = 0; ks < 4; ++ks) {
            uint32_t ph[4], pl[4];
            #pragma unroll
            for (int hf = 0; hf < 2; ++hf) {
                const int nt = 2 * ks + hf;
                const uint32_t w0 = (nt & 4) ? mw0.y : mw0.x;
                const uint32_t w1 = (nt & 4) ? mw1.y : mw1.x;
                const int bp = (nt * 8 + c2) & 31;
                float p;
                EX2F(p, S[nt][0]); if ((w0 >> bp) & 1)       p = 0.f; S[nt][0] = p; lrun0 += p;
                EX2F(p, S[nt][1]); if ((w0 >> (bp + 1)) & 1) p = 0.f; S[nt][1] = p; lrun0 += p;
                EX2F(p, S[nt][2]); if ((w1 >> bp) & 1)       p = 0.f; S[nt][2] = p; lrun1 += p;
                EX2F(p, S[nt][3]); if ((w1 >> (bp + 1)) & 1) p = 0.f; S[nt][3] = p; lrun1 += p;

                __nv_bfloat162 h01, h23, l01, l23;
                h01.x = __float2bfloat16(S[nt][0]);
                h01.y = __float2bfloat16(S[nt][1]);
                h23.x = __float2bfloat16(S[nt][2]);
                h23.y = __float2bfloat16(S[nt][3]);
                l01.x = __float2bfloat16(S[nt][0] - __bfloat162float(h01.x));
                l01.y = __float2bfloat16(S[nt][1] - __bfloat162float(h01.y));
                l23.x = __float2bfloat16(S[nt][2] - __bfloat162float(h23.x));
                l23.y = __float2bfloat16(S[nt][3] - __bfloat162float(h23.y));
                ph[hf * 2 + 0] = *(uint32_t*)&h01;
                ph[hf * 2 + 1] = *(uint32_t*)&h23;
                pl[hf * 2 + 0] = *(uint32_t*)&l01;
                pl[hf * 2 + 1] = *(uint32_t*)&l23;
            }
            uint32_t bf[4][4];
            #pragma unroll
            for (int g = 0; g < 4; ++g)
                LDM_X4(bf[g][0], bf[g][1], bf[g][2], bf[g][3],
                       vtb + (g * 16 + b_nrow) * 144 + (ks * 16 + b_koff) * 2);
            #pragma unroll
            for (int nt = 0; nt < 8; ++nt) {
                MMA_BF16(O[nt], ph, bf[nt >> 1][(nt & 1) * 2], bf[nt >> 1][(nt & 1) * 2 + 1]);
                MMA_BF16(O[nt], pl, bf[nt >> 1][(nt & 1) * 2], bf[nt >> 1][(nt & 1) * 2 + 1]);
            }
            #pragma unroll
            for (int g = 0; g < 4; ++g)
                LDM_X4(bf[g][0], bf[g][1], bf[g][2], bf[g][3],
                       vtb + 9216 + (g * 16 + b_nrow) * 144 + (ks * 16 + b_koff) * 2);
            #pragma unroll
            for (int nt = 0; nt < 8; ++nt)
                MMA_BF16(O[nt], ph, bf[nt >> 1][(nt & 1) * 2], bf[nt >> 1][(nt & 1) * 2 + 1]);
        }
    }

    lrun0 += __shfl_xor_sync(0xffffffffu, lrun0, 1);
    lrun0 += __shfl_xor_sync(0xffffffffu, lrun0, 2);
    lrun1 += __shfl_xor_sync(0xffffffffu, lrun1, 1);
    lrun1 += __shfl_xor_sync(0xffffffffu, lrun1, 2);

    const float inv0 = __fdividef(1.f, lrun0);
    const float inv1 = __fdividef(1.f, lrun1);
    #pragma unroll
    for (int nt = 0; nt < 8; ++nt) {
        const int d = h * DH + nt * 8 + c2;
        {
            const float v0 = O[nt][0] * inv0, v1 = O[nt][1] * inv0;
            const size_t idx = ((size_t)(b * SEQ) + row0) * DIM + d;
            __nv_bfloat162 hv, lv;
            hv.x = __float2bfloat16(v0); hv.y = __float2bfloat16(v1);
            lv.x = __float2bfloat16(v0 - __bfloat162float(hv.x));
            lv.y = __float2bfloat16(v1 - __bfloat162float(hv.y));
            *(__nv_bfloat162*)(oh + idx) = hv;
            *(__nv_bfloat162*)(ol + idx) = lv;
        }
        {
            const float v0 = O[nt][2] * inv1, v1 = O[nt][3] * inv1;
            const size_t idx = ((size_t)(b * SEQ) + row0 + 8) * DIM + d;
            __nv_bfloat162 hv, lv;
            hv.x = __float2bfloat16(v0); hv.y = __float2bfloat16(v1);
            lv.x = __float2bfloat16(v0 - __bfloat162float(hv.x));
            lv.y = __float2bfloat16(v1 - __bfloat162float(hv.y));
            *(__nv_bfloat162*)(oh + idx) = hv;
            *(__nv_bfloat162*)(ol + idx) = lv;
        }
    }
}

// ============================================================================
// Mega kernel roles:
//   [0,2048): bx%4==3 -> mask-pack CTA (512 total, interleaved); else
//             projection CTA (1536 total, z fastest).
//   [2048,3072): attention (waits on pack counter + projection flags)
//   [3072,3584): output GEMM (waits on attention flags)
// ============================================================================
struct MParams {
    const float *query, *key, *value;
    const int32_t* mask;
    const float *bq, *bk, *bv, *bo;
    const __nv_bfloat16 *wh, *wl;
    __nv_bfloat16 *qh, *ql, *kh, *kl, *vth, *vtl, *oh, *ol;
    float* out;
};

__global__ void __launch_bounds__(256, 2)
mega_kernel(MParams p)
{
    extern __shared__ __align__(128) char smem[];
    const int bx = blockIdx.x;
    const int tid = threadIdx.x;
    const int wid = tid >> 5, lane = tid & 31;
    const size_t WD = (size_t)DIM * DIM;

    if (bx < 2048) {
        if ((bx & 3) == 3) {
            // ---- mask pack role: warp ballots 32 ints -> 1 word, 8-way unroll
            const int gw = (bx >> 2) * 8 + wid;        // global warp id, 4096 warps
            #pragma unroll 1
            for (int pw = gw * 8; pw < NWORDS; pw += 4096 * 8) {
                int v[8];
                #pragma unroll
                for (int j = 0; j < 8; ++j)
                    v[j] = p.mask[(size_t)(pw + j) * 32 + lane];
                #pragma unroll
                for (int j = 0; j < 8; ++j) {
                    const uint32_t bits = __ballot_sync(0xffffffffu, v[j] != 0);
                    if (lane == 0) g_pmask[pw + j] = bits;
                }
            }
            __threadfence();
            __syncthreads();
            if (tid == 0) atomicAdd(&g_cntM, 1);
        } else {
            // ---- projection role (1536 CTAs)
            const int pj = bx - ((bx + 1) >> 2);
            const int z = pj % 3;
            const int r = pj / 3;
            const int xn = r & 7;
            const int ym = r >> 3;
            GArg a;
            if (z == 0)      a = { p.query, nullptr, nullptr, p.wh + 0 * WD, p.wl + 0 * WD,
                                   p.bq, nullptr, p.qh, p.ql, 0, QSCALE };
            else if (z == 1) a = { p.key,   nullptr, nullptr, p.wh + 1 * WD, p.wl + 1 * WD,
                                   p.bk, nullptr, p.kh, p.kl, 0, 1.0f };
            else             a = { p.value, nullptr, nullptr, p.wh + 2 * WD, p.wl + 2 * WD,
                                   p.bv, nullptr, p.vth, p.vtl, 1, 1.0f };
            gemm_body<1>(a, xn, ym, smem);
            __threadfence();
            __syncthreads();
            if (tid == 0) atomicAdd(&g_cntP[z][xn][ym >> 4], 1);
        }
    } else if (bx < 3072) {
        const int aidx = bx - 2048;
        const int h = aidx & 15;
        const int qt = (aidx >> 4) & 15;
        const int b = aidx >> 8;
        if (tid == 0) {
            const int nt = h >> 1;
            while (atomicAdd(&g_cntP[0][nt][b], 0) < 16) __nanosleep(256);
            while (atomicAdd(&g_cntP[1][nt][b], 0) < 16) __nanosleep(256);
            while (atomicAdd(&g_cntP[2][nt][b], 0) < 16) __nanosleep(256);
            while (atomicAdd(&g_cntM, 0) < 512) __nanosleep(256);
        }
        __syncthreads();
        __threadfence();
        attn_body(p.qh, p.ql, p.kh, p.kl, p.vth, p.vtl, p.oh, p.ol,
                  qt, b * 16 + h, smem);
        __threadfence();
        __syncthreads();
        if (tid == 0) atomicAdd(&g_cntA[b][qt], 1);
    } else {
        const int oidx = bx - 3072;
        const int xn = oidx & 7;
        const int ym = oidx >> 3;
        if (tid == 0)
            while (atomicAdd(&g_cntA[ym >> 4][ym & 15], 0) < 16) __nanosleep(256);
        __syncthreads();
        __threadfence();
        GArg a = { nullptr, p.oh, p.ol, p.wh + 3 * WD, p.wl + 3 * WD,
                   p.bo, p.out, nullptr, nullptr, 2, 1.0f };
        gemm_body<0>(a, xn, ym, smem);
    }
}

// ============================================================================
extern "C" void kernel_launch(void* const* d_in, const int* in_sizes, int n_in,
                              void* d_out, int out_size)
{
    const float* query = (const float*)d_in[0];
    const float* key_  = (const float*)d_in[1];
    const float* value = (const float*)d_in[2];
    const int32_t* mask = (const int32_t*)d_in[3];
    const float* Wq = (const float*)d_in[4];
    const float* bq = (const float*)d_in[5];
    const float* Wk = (const float*)d_in[6];
    const float* bk = (const float*)d_in[7];
    const float* Wv = (const float*)d_in[8];
    const float* bv = (const float*)d_in[9];
    const float* Wo = (const float*)d_in[10];
    const float* bo = (const float*)d_in[11];
    float* out = (float*)d_out;

    __nv_bfloat16 *wh, *wl, *qh, *ql, *kh, *kl, *vth, *vtl, *oh, *ol;
    cudaGetSymbolAddress((void**)&wh, g_wh);
    cudaGetSymbolAddress((void**)&wl, g_wl);
    cudaGetSymbolAddress((void**)&qh, g_qh);
    cudaGetSymbolAddress((void**)&ql, g_ql);
    cudaGetSymbolAddress((void**)&kh, g_kh);
    cudaGetSymbolAddress((void**)&kl, g_kl);
    cudaGetSymbolAddress((void**)&vth, g_vth);
    cudaGetSymbolAddress((void**)&vtl, g_vtl);
    cudaGetSymbolAddress((void**)&oh, g_oh);
    cudaGetSymbolAddress((void**)&ol, g_ol);
    const size_t WD = (size_t)DIM * DIM;

    cudaFuncSetAttribute(mega_kernel, cudaFuncAttributeMaxDynamicSharedMemorySize, MEGA_SMEM);

    // weight transpose+split + flag zeroing (one launch)
    TArg ta;
    ta.W[0] = Wq; ta.W[1] = Wk; ta.W[2] = Wv; ta.W[3] = Wo;
    for (int i = 0; i < 4; i++) { ta.Th[i] = wh + i * WD; ta.Tl[i] = wl + i * WD; }
    transpose_split_kernel<<<dim3(32, 32, 4), dim3(32, 8)>>>(ta);

    // fused mask-pack + projections + attention + output projection
    MParams mp;
    mp.query = query; mp.key = key_; mp.value = value; mp.mask = mask;
    mp.bq = bq; mp.bk = bk; mp.bv = bv; mp.bo = bo;
    mp.wh = wh; mp.wl = wl;
    mp.qh = qh; mp.ql = ql; mp.kh = kh; mp.kl = kl;
    mp.vth = vth; mp.vtl = vtl; mp.oh = oh; mp.ol = ol;
    mp.out = out;
    mega_kernel<<<3584, 256, MEGA_SMEM>>>(mp);
}

// round 15
// speedup vs baseline: 1.0606x; 1.0606x over previous
#include <cuda_runtime.h>
#include <cuda_bf16.h>
#include <cstdint>
#include <cstddef>

#define H      16
#define BSZ    4
#define SEQ    2048
#define DIM    1024
#define DH     64
#define MROWS  (BSZ * SEQ)   // 8192
#define QSCALE 0.1803368801111244f   // 0.125 * log2(e)
#define NWORDS (BSZ * SEQ * H * (SEQ / 32))   // 8388608 packed mask words

// ---- scratch (module-scope, no runtime allocation) -------------------------
__device__ __nv_bfloat16 g_wh[4][DIM * DIM];      // W^T hi  [n][k]
__device__ __nv_bfloat16 g_wl[4][DIM * DIM];      // W^T lo
__device__ __nv_bfloat16 g_qh[BSZ * H * SEQ * DH], g_ql[BSZ * H * SEQ * DH];
__device__ __nv_bfloat16 g_kh[BSZ * H * SEQ * DH], g_kl[BSZ * H * SEQ * DH];
__device__ __nv_bfloat16 g_vth[BSZ * H * DH * SEQ], g_vtl[BSZ * H * DH * SEQ]; // V^T [B,H,DH,S]
__device__ __nv_bfloat16 g_oh[MROWS * DIM], g_ol[MROWS * DIM];                 // attn out
__device__ uint32_t g_pmask[NWORDS];              // packed mask (33.5 MB)

// ---- dataflow flags (zeroed inside transpose kernel each replay) ------------
__device__ int g_cntP[3][8][BSZ];   // [z=Q/K/V][ntile][b] -> reaches 16
__device__ int g_cntA[BSZ][16];     // [b][qtile]          -> reaches 16
__device__ int g_cntM[BSZ][16];     // [b][qtile] mask-pack regions -> reaches 8

// ============================================================================
// PTX helpers
// ============================================================================
__device__ __forceinline__ uint32_t smem_u32(const void* p) {
    uint32_t a;
    asm("{ .reg .u64 t; cvta.to.shared.u64 t, %1; cvt.u32.u64 %0, t; }"
        : "=r"(a) : "l"(p));
    return a;
}

#define CP_ASYNC16(dst, src) \
    asm volatile("cp.async.cg.shared.global [%0], [%1], 16;" \
                 :: "r"(dst), "l"(src) : "memory")
#define CP_COMMIT() asm volatile("cp.async.commit_group;" ::: "memory")
#define CP_WAIT(n)  asm volatile("cp.async.wait_group %0;" :: "n"(n) : "memory")

#define LDM_X4(r0, r1, r2, r3, addr) \
    asm volatile("ldmatrix.sync.aligned.m8n8.x4.shared.b16 {%0,%1,%2,%3}, [%4];" \
                 : "=r"(r0), "=r"(r1), "=r"(r2), "=r"(r3) : "r"(addr))

#define MMA_BF16(d, a, b0, b1)                                                \
    asm volatile("mma.sync.aligned.m16n8k16.row.col.f32.bf16.bf16.f32 "       \
                 "{%0,%1,%2,%3}, {%4,%5,%6,%7}, {%8,%9}, {%0,%1,%2,%3};"      \
                 : "+f"((d)[0]), "+f"((d)[1]), "+f"((d)[2]), "+f"((d)[3])     \
                 : "r"((a)[0]), "r"((a)[1]), "r"((a)[2]), "r"((a)[3]),        \
                   "r"(b0), "r"(b1))

#define EX2F(d, s) asm("ex2.approx.f32 %0, %1;" : "=f"(d) : "f"(s))

// XOR-swizzled offset for 64B-row bf16 tiles (r = row, c16 = 16B column 0..3).
#define SWZ(r, c16) (((r) << 6) + ((((c16) ^ (((r) >> 1) & 3))) << 4))

__device__ __forceinline__ void split2(float2 v, uint32_t& hi, uint32_t& lo) {
    __nv_bfloat162 h;
    h.x = __float2bfloat16(v.x);
    h.y = __float2bfloat16(v.y);
    __nv_bfloat162 l;
    l.x = __float2bfloat16(v.x - __bfloat162float(h.x));
    l.y = __float2bfloat16(v.y - __bfloat162float(h.y));
    hi = *(uint32_t*)&h;
    lo = *(uint32_t*)&l;
}

// ============================================================================
// Prologue: weight transpose+split (z = 4 weights); block (0,0,0) also zeroes
// the dataflow flags (kernel completes before mega_kernel starts).
// ============================================================================
struct TArg { const float* W[4]; __nv_bfloat16* Th[4]; __nv_bfloat16* Tl[4]; };

__global__ void __launch_bounds__(256)
transpose_split_kernel(TArg p)
{
    __shared__ float t[32][33];
    const int z = blockIdx.z;
    if (z == 0 && blockIdx.x == 0 && blockIdx.y == 0) {
        const int tid = threadIdx.y * 32 + threadIdx.x;
        if (tid < 3 * 8 * BSZ) ((int*)g_cntP)[tid] = 0;
        if (tid < BSZ * 16)    ((int*)g_cntA)[tid] = 0;
        if (tid < BSZ * 16)    ((int*)g_cntM)[tid] = 0;
    }
    const float* W = p.W[z];
    __nv_bfloat16* Th = p.Th[z];
    __nv_bfloat16* Tl = p.Tl[z];
    const int tx = threadIdx.x, ty = threadIdx.y;       // 32 x 8
    const int nb = blockIdx.x * 32, kb = blockIdx.y * 32;
    #pragma unroll
    for (int i = 0; i < 4; i++)
        t[ty + i * 8][tx] = W[(size_t)(kb + ty + i * 8) * DIM + nb + tx];
    __syncthreads();
    #pragma unroll
    for (int i = 0; i < 4; i++) {
        const float v = t[tx][ty + i * 8];
        const __nv_bfloat16 h = __float2bfloat16(v);
        Th[(size_t)(nb + ty + i * 8) * DIM + kb + tx] = h;
        Tl[(size_t)(nb + ty + i * 8) * DIM + kb + tx] =
            __float2bfloat16(v - __bfloat162float(h));
    }
}

// ============================================================================
// GEMM body (unchanged from R13). 3-stage cp.async, XOR-swizzled bf16 tiles.
// ============================================================================
#define GSTRIDE    36864
#define MEGA_SMEM  110592

struct GArg {
    const float* Af;
    const __nv_bfloat16 *Ah, *Al;
    const __nv_bfloat16 *Wh, *Wl;
    const float* bias;
    float* Cf;
    __nv_bfloat16 *Ch, *Cl;
    int omode;
    float scale;
};

template <int AFP32>
__device__ void gemm_body(const GArg& a, int bxx, int byy, char* smem)
{
    const uint32_t sb = smem_u32(smem);
    const int tid = threadIdx.x;
    const int wid = tid >> 5, lane = tid & 31;
    const int wm = wid & 3, wn = wid >> 2;
    const int m0 = byy * 128, n0 = bxx * 128;

    const int a_row  = lane & 15;
    const int a_c16  = (lane >> 4) & 1;
    const int b_nrow = (lane & 7) + ((lane >> 4) & 1) * 8;
    const int b_c16  = (lane >> 3) & 1;

    float acc[2][8][4];
    #pragma unroll
    for (int i = 0; i < 2; i++)
        #pragma unroll
        for (int j = 0; j < 8; j++)
            #pragma unroll
            for (int k = 0; k < 4; k++) acc[i][j][k] = 0.f;

    const int wOff = AFP32 ? 20480 : 16384;

    auto issue = [&](int it) {
        const int kc = it * 32;
        const uint32_t st = sb + (it % 3) * GSTRIDE;
        if (AFP32) {
            #pragma unroll
            for (int i = 0; i < 4; i++) {
                const int idx = tid + i * 256;
                const int r = idx >> 3, c = idx & 7;
                CP_ASYNC16(st + r * 160 + c * 16,
                           a.Af + (size_t)(m0 + r) * DIM + kc + c * 4);
            }
            #pragma unroll
            for (int i = 0; i < 2; i++) {
                const int idx = tid + i * 256;
                const int r = idx >> 2, c16 = idx & 3;
                const uint32_t o = SWZ(r, c16);
                const size_t gw = (size_t)(n0 + r) * DIM + kc + c16 * 8;
                CP_ASYNC16(st + 20480 + o, a.Wh + gw);
                CP_ASYNC16(st + 28672 + o, a.Wl + gw);
            }
        } else {
            #pragma unroll
            for (int i = 0; i < 2; i++) {
                const int idx = tid + i * 256;
                const int r = idx >> 2, c16 = idx & 3;
                const uint32_t o = SWZ(r, c16);
                const size_t ga = (size_t)(m0 + r) * DIM + kc + c16 * 8;
                const size_t gw = (size_t)(n0 + r) * DIM + kc + c16 * 8;
                CP_ASYNC16(st + o,         a.Ah + ga);
                CP_ASYNC16(st + 8192 + o,  a.Al + ga);
                CP_ASYNC16(st + 16384 + o, a.Wh + gw);
                CP_ASYNC16(st + 24576 + o, a.Wl + gw);
            }
        }
        CP_COMMIT();
    };

    issue(0);
    issue(1);

    #pragma unroll 1
    for (int it = 0; it < 32; ++it) {
        if (it + 1 < 32) { CP_WAIT(1); } else { CP_WAIT(0); }
        __syncthreads();
        if (it + 2 < 32) issue(it + 2);

        const uint32_t st = sb + (it % 3) * GSTRIDE;
        const char* stc = smem + (it % 3) * GSTRIDE;

        #pragma unroll
        for (int ks = 0; ks < 2; ++ks) {
            uint32_t ah[2][4], al[2][4];
            if (AFP32) {
                const int cb = ks * 16 + (lane & 3) * 2;
                #pragma unroll
                for (int mt = 0; mt < 2; ++mt) {
                    const int r = wm * 32 + mt * 16 + (lane >> 2);
                    const char* base = stc + (size_t)r * 160 + cb * 4;
                    const float2 v00 = *(const float2*)(base);
                    const float2 v01 = *(const float2*)(base + 8 * 160);
                    const float2 v10 = *(const float2*)(base + 32);
                    const float2 v11 = *(const float2*)(base + 8 * 160 + 32);
                    split2(v00, ah[mt][0], al[mt][0]);
                    split2(v01, ah[mt][1], al[mt][1]);
                    split2(v10, ah[mt][2], al[mt][2]);
                    split2(v11, ah[mt][3], al[mt][3]);
                }
            } else {
                #pragma unroll
                for (int mt = 0; mt < 2; ++mt) {
                    const int ar = wm * 32 + mt * 16 + a_row;
                    const uint32_t ao = SWZ(ar, ks * 2 + a_c16);
                    LDM_X4(ah[mt][0], ah[mt][1], ah[mt][2], ah[mt][3], st + ao);
                    LDM_X4(al[mt][0], al[mt][1], al[mt][2], al[mt][3], st + 8192 + ao);
                }
            }
            uint32_t b[4][4];
            #pragma unroll
            for (int g = 0; g < 4; ++g) {
                const int br = wn * 64 + g * 16 + b_nrow;
                LDM_X4(b[g][0], b[g][1], b[g][2], b[g][3],
                       st + wOff + SWZ(br, ks * 2 + b_c16));
            }
            #pragma unroll
            for (int mt = 0; mt < 2; ++mt)
                #pragma unroll
                for (int nt = 0; nt < 8; ++nt) {
                    MMA_BF16(acc[mt][nt], ah[mt],
                             b[nt >> 1][(nt & 1) * 2], b[nt >> 1][(nt & 1) * 2 + 1]);
                    MMA_BF16(acc[mt][nt], al[mt],
                             b[nt >> 1][(nt & 1) * 2], b[nt >> 1][(nt & 1) * 2 + 1]);
                }
            #pragma unroll
            for (int g = 0; g < 4; ++g) {
                const int br = wn * 64 + g * 16 + b_nrow;
                LDM_X4(b[g][0], b[g][1], b[g][2], b[g][3],
                       st + wOff + 8192 + SWZ(br, ks * 2 + b_c16));
            }
            #pragma unroll
            for (int mt = 0; mt < 2; ++mt)
                #pragma unroll
                for (int nt = 0; nt < 8; ++nt)
                    MMA_BF16(acc[mt][nt], ah[mt],
                             b[nt >> 1][(nt & 1) * 2], b[nt >> 1][(nt & 1) * 2 + 1]);
        }
    }

    // ---- epilogue
    const int r0l = lane >> 2, c0 = (lane & 3) * 2;
    #pragma unroll
    for (int mt = 0; mt < 2; ++mt) {
        #pragma unroll
        for (int nt = 0; nt < 8; ++nt) {
            const int n = n0 + wn * 64 + nt * 8 + c0;
            const float bx = a.bias[n], by = a.bias[n + 1];
            #pragma unroll
            for (int half = 0; half < 2; ++half) {
                const int r = m0 + wm * 32 + mt * 16 + r0l + half * 8;
                const float vx = (acc[mt][nt][half * 2 + 0] + bx) * a.scale;
                const float vy = (acc[mt][nt][half * 2 + 1] + by) * a.scale;
                if (a.omode == 2) {
                    *(float2*)&a.Cf[(size_t)r * DIM + n] = make_float2(vx, vy);
                } else {
                    const int bb = r >> 11, s = r & (SEQ - 1);
                    const int hh = n >> 6, d = n & (DH - 1);
                    const __nv_bfloat16 hx = __float2bfloat16(vx);
                    const __nv_bfloat16 hy = __float2bfloat16(vy);
                    const __nv_bfloat16 lx = __float2bfloat16(vx - __bfloat162float(hx));
                    const __nv_bfloat16 ly = __float2bfloat16(vy - __bfloat162float(hy));
                    if (a.omode == 0) {
                        const size_t idx = ((size_t)(bb * H + hh) * SEQ + s) * DH + d;
                        __nv_bfloat162 hv; hv.x = hx; hv.y = hy;
                        __nv_bfloat162 lv; lv.x = lx; lv.y = ly;
                        *(__nv_bfloat162*)(a.Ch + idx) = hv;
                        *(__nv_bfloat162*)(a.Cl + idx) = lv;
                    } else {
                        const size_t base = (size_t)(bb * H + hh) * DH;
                        a.Ch[(base + d) * SEQ + s]     = hx;
                        a.Ch[(base + d + 1) * SEQ + s] = hy;
                        a.Cl[(base + d) * SEQ + s]     = lx;
                        a.Cl[(base + d + 1) * SEQ + s] = ly;
                    }
                }
            }
        }
    }
}

// ============================================================================
// Attention body: packed-mask version (2x LDG.64 packed words per tile).
// ============================================================================
#define ATTN_QH   73728
#define ATTN_QL   92160

__device__ void attn_body(
        const __nv_bfloat16* __restrict__ qh, const __nv_bfloat16* __restrict__ ql,
        const __nv_bfloat16* __restrict__ kh, const __nv_bfloat16* __restrict__ kl,
        const __nv_bfloat16* __restrict__ vth, const __nv_bfloat16* __restrict__ vtl,
        __nv_bfloat16* __restrict__ oh, __nv_bfloat16* __restrict__ ol,
        int qt, int bh, char* smem)
{
    const uint32_t sb = smem_u32(smem);
    const int tid = threadIdx.x;
    const int wid = tid >> 5, lane = tid & 31;
    const int b = bh >> 4, h = bh & 15;
    const int q0 = qt * 128;
    const int wrow = wid * 16;

    const int a_row  = lane & 15;
    const int a_koff = ((lane >> 4) & 1) * 8;
    const int b_nrow = (lane & 7) + ((lane >> 4) & 1) * 8;
    const int b_koff = ((lane >> 3) & 1) * 8;
    const int r0 = lane >> 2, c2 = (lane & 3) * 2;

    #pragma unroll
    for (int i = 0; i < 8; i++) {
        const int idx = tid + i * 256;
        const int part = idx >> 10;
        const int id = idx & 1023;
        const int r = id >> 3, c = id & 7;
        const __nv_bfloat16* src = (part ? ql : qh)
            + ((size_t)bh * SEQ + q0 + r) * DH + c * 8;
        CP_ASYNC16(sb + (part ? ATTN_QL : ATTN_QH) + r * 144 + c * 16, src);
    }
    CP_COMMIT();

    float O[8][4];
    #pragma unroll
    for (int nt = 0; nt < 8; nt++)
        #pragma unroll
        for (int q = 0; q < 4; q++) O[nt][q] = 0.f;
    float lrun0 = 0.f, lrun1 = 0.f;

    const int row0 = q0 + wrow + r0;
    const uint32_t* pm0 = g_pmask + ((size_t)(b * SEQ + row0) * H + h) * 64;
    const uint32_t* pm1 = pm0 + (size_t)8 * H * 64;

    auto issue_kv = [&](int kt) {
        const int k0i = kt * 64;
        const uint32_t st = sb + (kt & 1) * 36864;
        #pragma unroll
        for (int i = 0; i < 8; i++) {
            const int idx = tid + i * 256;
            const int part = idx >> 9;
            const int id = idx & 511;
            const int r = id >> 3, c = id & 7;
            const __nv_bfloat16* src;
            if (part == 0)      src = kh  + ((size_t)bh * SEQ + k0i + r) * DH + c * 8;
            else if (part == 1) src = kl  + ((size_t)bh * SEQ + k0i + r) * DH + c * 8;
            else if (part == 2) src = vth + ((size_t)bh * DH + r) * SEQ + k0i + c * 8;
            else                src = vtl + ((size_t)bh * DH + r) * SEQ + k0i + c * 8;
            CP_ASYNC16(st + part * 9216 + r * 144 + c * 16, src);
        }
        CP_COMMIT();
    };

    issue_kv(0);

    #pragma unroll 1
    for (int kt = 0; kt < 32; ++kt) {
        const int k0 = kt * 64;
        CP_WAIT(0);
        __syncthreads();
        if (kt + 1 < 32) issue_kv(kt + 1);

        const uint32_t kbase = sb + (kt & 1) * 36864;
        const uint32_t qho = sb + ATTN_QH + (wrow + a_row) * 144 + a_koff * 2;
        const uint32_t qlo = sb + ATTN_QL + (wrow + a_row) * 144 + a_koff * 2;

        const uint2 mw0 = *(const uint2*)(pm0 + (k0 >> 5));
        const uint2 mw1 = *(const uint2*)(pm1 + (k0 >> 5));

        float S[8][4];
        #pragma unroll
        for (int nt = 0; nt < 8; nt++)
            #pragma unroll
            for (int q = 0; q < 4; q++) S[nt][q] = 0.f;

        #pragma unroll
        for (int ks = 0; ks < 4; ++ks) {
            uint32_t qhf[4], qlf[4];
            LDM_X4(qhf[0], qhf[1], qhf[2], qhf[3], qho + ks * 32);
            LDM_X4(qlf[0], qlf[1], qlf[2], qlf[3], qlo + ks * 32);
            uint32_t bf[4][4];
            #pragma unroll
            for (int g = 0; g < 4; ++g)
                LDM_X4(bf[g][0], bf[g][1], bf[g][2], bf[g][3],
                       kbase + (g * 16 + b_nrow) * 144 + (ks * 16 + b_koff) * 2);
            #pragma unroll
            for (int nt = 0; nt < 8; ++nt) {
                MMA_BF16(S[nt], qhf, bf[nt >> 1][(nt & 1) * 2], bf[nt >> 1][(nt & 1) * 2 + 1]);
                MMA_BF16(S[nt], qlf, bf[nt >> 1][(nt & 1) * 2], bf[nt >> 1][(nt & 1) * 2 + 1]);
            }
            #pragma unroll
            for (int g = 0; g < 4; ++g)
                LDM_X4(bf[g][0], bf[g][1], bf[g][2], bf[g][3],
                       kbase + 9216 + (g * 16 + b_nrow) * 144 + (ks * 16 + b_koff) * 2);
            #pragma unroll
            for (int nt = 0; nt < 8; ++nt)
                MMA_BF16(S[nt], qhf, bf[nt >> 1][(nt & 1) * 2], bf[nt >> 1][(nt & 1) * 2 + 1]);
        }

        const uint32_t vtb = kbase + 18432;
        #pragma unroll
        for (int ks = 0; ks < 4; ++ks) {
            uint32_t ph[4], pl[4];
            #pragma unroll
            for (int hf = 0; hf < 2; ++hf) {
                const int nt = 2 * ks + hf;
                const uint32_t w0 = (nt & 4) ? mw0.y : mw0.x;
                const uint32_t w1 = (nt & 4) ? mw1.y : mw1.x;
                const int bp = (nt * 8 + c2) & 31;
                float p;
                EX2F(p, S[nt][0]); if ((w0 >> bp) & 1)       p = 0.f; S[nt][0] = p; lrun0 += p;
                EX2F(p, S[nt][1]); if ((w0 >> (bp + 1)) & 1) p = 0.f; S[nt][1] = p; lrun0 += p;
                EX2F(p, S[nt][2]); if ((w1 >> bp) & 1)       p = 0.f; S[nt][2] = p; lrun1 += p;
                EX2F(p, S[nt][3]); if ((w1 >> (bp + 1)) & 1) p = 0.f; S[nt][3] = p; lrun1 += p;

                __nv_bfloat162 h01, h23, l01, l23;
                h01.x = __float2bfloat16(S[nt][0]);
                h01.y = __float2bfloat16(S[nt][1]);
                h23.x = __float2bfloat16(S[nt][2]);
                h23.y = __float2bfloat16(S[nt][3]);
                l01.x = __float2bfloat16(S[nt][0] - __bfloat162float(h01.x));
                l01.y = __float2bfloat16(S[nt][1] - __bfloat162float(h01.y));
                l23.x = __float2bfloat16(S[nt][2] - __bfloat162float(h23.x));
                l23.y = __float2bfloat16(S[nt][3] - __bfloat162float(h23.y));
                ph[hf * 2 + 0] = *(uint32_t*)&h01;
                ph[hf * 2 + 1] = *(uint32_t*)&h23;
                pl[hf * 2 + 0] = *(uint32_t*)&l01;
                pl[hf * 2 + 1] = *(uint32_t*)&l23;
            }
            uint32_t bf[4][4];
            #pragma unroll
            for (int g = 0; g < 4; ++g)
                LDM_X4(bf[g][0], bf[g][1], bf[g][2], bf[g][3],
                       vtb + (g * 16 + b_nrow) * 144 + (ks * 16 + b_koff) * 2);
            #pragma unroll
            for (int nt = 0; nt < 8; ++nt) {
                MMA_BF16(O[nt], ph, bf[nt >> 1][(nt & 1) * 2], bf[nt >> 1][(nt & 1) * 2 + 1]);
                MMA_BF16(O[nt], pl, bf[nt >> 1][(nt & 1) * 2], bf[nt >> 1][(nt & 1) * 2 + 1]);
            }
            #pragma unroll
            for (int g = 0; g < 4; ++g)
                LDM_X4(bf[g][0], bf[g][1], bf[g][2], bf[g][3],
                       vtb + 9216 + (g * 16 + b_nrow) * 144 + (ks * 16 + b_koff) * 2);
            #pragma unroll
            for (int nt = 0; nt < 8; ++nt)
                MMA_BF16(O[nt], ph, bf[nt >> 1][(nt & 1) * 2], bf[nt >> 1][(nt & 1) * 2 + 1]);
        }
    }

    lrun0 += __shfl_xor_sync(0xffffffffu, lrun0, 1);
    lrun0 += __shfl_xor_sync(0xffffffffu, lrun0, 2);
    lrun1 += __shfl_xor_sync(0xffffffffu, lrun1, 1);
    lrun1 += __shfl_xor_sync(0xffffffffu, lrun1, 2);

    const float inv0 = __fdividef(1.f, lrun0);
    const float inv1 = __fdividef(1.f, lrun1);
    #pragma unroll
    for (int nt = 0; nt < 8; ++nt) {
        const int d = h * DH + nt * 8 + c2;
        {
            const float v0 = O[nt][0] * inv0, v1 = O[nt][1] * inv0;
            const size_t idx = ((size_t)(b * SEQ) + row0) * DIM + d;
            __nv_bfloat162 hv, lv;
            hv.x = __float2bfloat16(v0); hv.y = __float2bfloat16(v1);
            lv.x = __float2bfloat16(v0 - __bfloat162float(hv.x));
            lv.y = __float2bfloat16(v1 - __bfloat162float(hv.y));
            *(__nv_bfloat162*)(oh + idx) = hv;
            *(__nv_bfloat162*)(ol + idx) = lv;
        }
        {
            const float v0 = O[nt][2] * inv1, v1 = O[nt][3] * inv1;
            const size_t idx = ((size_t)(b * SEQ) + row0 + 8) * DIM + d;
            __nv_bfloat162 hv, lv;
            hv.x = __float2bfloat16(v0); hv.y = __float2bfloat16(v1);
            lv.x = __float2bfloat16(v0 - __bfloat162float(hv.x));
            lv.y = __float2bfloat16(v1 - __bfloat162float(hv.y));
            *(__nv_bfloat162*)(oh + idx) = hv;
            *(__nv_bfloat162*)(ol + idx) = lv;
        }
    }
}

// ============================================================================
// Mega kernel roles:
//   [0,2048): bx%4==3 -> mask-pack CTA (512, region pk>>3 = b*16+qt, 8 subs
//             each); else projection CTA (1536, z fastest).
//   [2048,3072): attention (waits on its region's pack counter == 8 +
//                projection flags) — NO global pack barrier.
//   [3072,3584): output GEMM (waits on attention flags)
// ============================================================================
struct MParams {
    const float *query, *key, *value;
    const int32_t* mask;
    const float *bq, *bk, *bv, *bo;
    const __nv_bfloat16 *wh, *wl;
    __nv_bfloat16 *qh, *ql, *kh, *kl, *vth, *vtl, *oh, *ol;
    float* out;
};

__global__ void __launch_bounds__(256, 2)
mega_kernel(MParams p)
{
    extern __shared__ __align__(128) char smem[];
    const int bx = blockIdx.x;
    const int tid = threadIdx.x;
    const int wid = tid >> 5, lane = tid & 31;
    const size_t WD = (size_t)DIM * DIM;

    if (bx < 2048) {
        if ((bx & 3) == 3) {
            // ---- mask pack role: region = pk>>3 (b*16+qt), sub-slice pk&7.
            // Region words are contiguous: reg*131072 .. +131072.
            const int pk = bx >> 2;              // 0..511
            const int reg = pk >> 3;             // 0..63
            const int sub = pk & 7;
            const size_t base = (size_t)reg * 131072 + (size_t)sub * 16384
                              + (size_t)wid * 2048;
            #pragma unroll 1
            for (int j8 = 0; j8 < 2048; j8 += 8) {
                const size_t pw = base + j8;
                int v[8];
                #pragma unroll
                for (int j = 0; j < 8; ++j)
                    v[j] = p.mask[(pw + j) * 32 + lane];
                #pragma unroll
                for (int j = 0; j < 8; ++j) {
                    const uint32_t bits = __ballot_sync(0xffffffffu, v[j] != 0);
                    if (lane == 0) g_pmask[pw + j] = bits;
                }
            }
            __threadfence();
            __syncthreads();
            if (tid == 0) atomicAdd(&g_cntM[reg >> 4][reg & 15], 1);
        } else {
            // ---- projection role (1536 CTAs)
            const int pj = bx - ((bx + 1) >> 2);
            const int z = pj % 3;
            const int r = pj / 3;
            const int xn = r & 7;
            const int ym = r >> 3;
            GArg a;
            if (z == 0)      a = { p.query, nullptr, nullptr, p.wh + 0 * WD, p.wl + 0 * WD,
                                   p.bq, nullptr, p.qh, p.ql, 0, QSCALE };
            else if (z == 1) a = { p.key,   nullptr, nullptr, p.wh + 1 * WD, p.wl + 1 * WD,
                                   p.bk, nullptr, p.kh, p.kl, 0, 1.0f };
            else             a = { p.value, nullptr, nullptr, p.wh + 2 * WD, p.wl + 2 * WD,
                                   p.bv, nullptr, p.vth, p.vtl, 1, 1.0f };
            gemm_body<1>(a, xn, ym, smem);
            __threadfence();
            __syncthreads();
            if (tid == 0) atomicAdd(&g_cntP[z][xn][ym >> 4], 1);
        }
    } else if (bx < 3072) {
        const int aidx = bx - 2048;
        const int h = aidx & 15;
        const int qt = (aidx >> 4) & 15;
        const int b = aidx >> 8;
        if (tid == 0) {
            const int nt = h >> 1;
            while (atomicAdd(&g_cntP[0][nt][b], 0) < 16) __nanosleep(256);
            while (atomicAdd(&g_cntP[1][nt][b], 0) < 16) __nanosleep(256);
            while (atomicAdd(&g_cntP[2][nt][b], 0) < 16) __nanosleep(256);
            while (atomicAdd(&g_cntM[b][qt], 0) < 8)     __nanosleep(256);
        }
        __syncthreads();
        __threadfence();
        attn_body(p.qh, p.ql, p.kh, p.kl, p.vth, p.vtl, p.oh, p.ol,
                  qt, b * 16 + h, smem);
        __threadfence();
        __syncthreads();
        if (tid == 0) atomicAdd(&g_cntA[b][qt], 1);
    } else {
        const int oidx = bx - 3072;
        const int xn = oidx & 7;
        const int ym = oidx >> 3;
        if (tid == 0)
            while (atomicAdd(&g_cntA[ym >> 4][ym & 15], 0) < 16) __nanosleep(256);
        __syncthreads();
        __threadfence();
        GArg a = { nullptr, p.oh, p.ol, p.wh + 3 * WD, p.wl + 3 * WD,
                   p.bo, p.out, nullptr, nullptr, 2, 1.0f };
        gemm_body<0>(a, xn, ym, smem);
    }
}

// ============================================================================
extern "C" void kernel_launch(void* const* d_in, const int* in_sizes, int n_in,
                              void* d_out, int out_size)
{
    const float* query = (const float*)d_in[0];
    const float* key_  = (const float*)d_in[1];
    const float* value = (const float*)d_in[2];
    const int32_t* mask = (const int32_t*)d_in[3];
    const float* Wq = (const float*)d_in[4];
    const float* bq = (const float*)d_in[5];
    const float* Wk = (const float*)d_in[6];
    const float* bk = (const float*)d_in[7];
    const float* Wv = (const float*)d_in[8];
    const float* bv = (const float*)d_in[9];
    const float* Wo = (const float*)d_in[10];
    const float* bo = (const float*)d_in[11];
    float* out = (float*)d_out;

    __nv_bfloat16 *wh, *wl, *qh, *ql, *kh, *kl, *vth, *vtl, *oh, *ol;
    cudaGetSymbolAddress((void**)&wh, g_wh);
    cudaGetSymbolAddress((void**)&wl, g_wl);
    cudaGetSymbolAddress((void**)&qh, g_qh);
    cudaGetSymbolAddress((void**)&ql, g_ql);
    cudaGetSymbolAddress((void**)&kh, g_kh);
    cudaGetSymbolAddress((void**)&kl, g_kl);
    cudaGetSymbolAddress((void**)&vth, g_vth);
    cudaGetSymbolAddress((void**)&vtl, g_vtl);
    cudaGetSymbolAddress((void**)&oh, g_oh);
    cudaGetSymbolAddress((void**)&ol, g_ol);
    const size_t WD = (size_t)DIM * DIM;

    cudaFuncSetAttribute(mega_kernel, cudaFuncAttributeMaxDynamicSharedMemorySize, MEGA_SMEM);

    // weight transpose+split + flag zeroing (one launch)
    TArg ta;
    ta.W[0] = Wq; ta.W[1] = Wk; ta.W[2] = Wv; ta.W[3] = Wo;
    for (int i = 0; i < 4; i++) { ta.Th[i] = wh + i * WD; ta.Tl[i] = wl + i * WD; }
    transpose_split_kernel<<<dim3(32, 32, 4), dim3(32, 8)>>>(ta);

    // fused mask-pack + projections + attention + output projection
    MParams mp;
    mp.query = query; mp.key = key_; mp.value = value; mp.mask = mask;
    mp.bq = bq; mp.bk = bk; mp.bv = bv; mp.bo = bo;
    mp.wh = wh; mp.wl = wl;
    mp.qh = qh; mp.ql = ql; mp.kh = kh; mp.kl = kl;
    mp.vth = vth; mp.vtl = vtl; mp.oh = oh; mp.ol = ol;
    mp.out = out;
    mega_kernel<<<3584, 256, MEGA_SMEM>>>(mp);
}

// round 16
// speedup vs baseline: 1.2487x; 1.1773x over previous
#include <cuda_runtime.h>
#include <cuda_bf16.h>
#include <cstdint>
#include <cstddef>

#define H      16
#define BSZ    4
#define SEQ    2048
#define DIM    1024
#define DH     64
#define MROWS  (BSZ * SEQ)   // 8192
#define QSCALE 0.1803368801111244f   // 0.125 * log2(e)

// ---- scratch (module-scope, no runtime allocation) -------------------------
__device__ __nv_bfloat16 g_wh[4][DIM * DIM];      // W^T hi  [n][k]
__device__ __nv_bfloat16 g_wl[4][DIM * DIM];      // W^T lo
__device__ __nv_bfloat16 g_qh[BSZ * H * SEQ * DH], g_ql[BSZ * H * SEQ * DH];
__device__ __nv_bfloat16 g_kh[BSZ * H * SEQ * DH], g_kl[BSZ * H * SEQ * DH];
__device__ __nv_bfloat16 g_vth[BSZ * H * DH * SEQ], g_vtl[BSZ * H * DH * SEQ]; // V^T [B,H,DH,S]
__device__ __nv_bfloat16 g_oh[MROWS * DIM], g_ol[MROWS * DIM];                 // attn out

// ---- dataflow flags (zeroed inside transpose kernel each replay) ------------
__device__ int g_cntP[3][8][BSZ];   // [z=Q/K/V][ntile][b] -> reaches 16
__device__ int g_cntA[BSZ][16];     // [b][qtile]          -> reaches 16

// ============================================================================
// PTX helpers
// ============================================================================
__device__ __forceinline__ uint32_t smem_u32(const void* p) {
    uint32_t a;
    asm("{ .reg .u64 t; cvta.to.shared.u64 t, %1; cvt.u32.u64 %0, t; }"
        : "=r"(a) : "l"(p));
    return a;
}

#define CP_ASYNC16(dst, src) \
    asm volatile("cp.async.cg.shared.global [%0], [%1], 16;" \
                 :: "r"(dst), "l"(src) : "memory")
#define CP_COMMIT() asm volatile("cp.async.commit_group;" ::: "memory")
#define CP_WAIT(n)  asm volatile("cp.async.wait_group %0;" :: "n"(n) : "memory")

#define LDM_X4(r0, r1, r2, r3, addr) \
    asm volatile("ldmatrix.sync.aligned.m8n8.x4.shared.b16 {%0,%1,%2,%3}, [%4];" \
                 : "=r"(r0), "=r"(r1), "=r"(r2), "=r"(r3) : "r"(addr))

#define MMA_BF16(d, a, b0, b1)                                                \
    asm volatile("mma.sync.aligned.m16n8k16.row.col.f32.bf16.bf16.f32 "       \
                 "{%0,%1,%2,%3}, {%4,%5,%6,%7}, {%8,%9}, {%0,%1,%2,%3};"      \
                 : "+f"((d)[0]), "+f"((d)[1]), "+f"((d)[2]), "+f"((d)[3])     \
                 : "r"((a)[0]), "r"((a)[1]), "r"((a)[2]), "r"((a)[3]),        \
                   "r"(b0), "r"(b1))

#define EX2F(d, s) asm("ex2.approx.f32 %0, %1;" : "=f"(d) : "f"(s))

// XOR-swizzled offset for 64B-row bf16 tiles (r = row, c16 = 16B column 0..3).
#define SWZ(r, c16) (((r) << 6) + ((((c16) ^ (((r) >> 1) & 3))) << 4))

__device__ __forceinline__ void split2(float2 v, uint32_t& hi, uint32_t& lo) {
    __nv_bfloat162 h;
    h.x = __float2bfloat16(v.x);
    h.y = __float2bfloat16(v.y);
    __nv_bfloat162 l;
    l.x = __float2bfloat16(v.x - __bfloat162float(h.x));
    l.y = __float2bfloat16(v.y - __bfloat162float(h.y));
    hi = *(uint32_t*)&h;
    lo = *(uint32_t*)&l;
}

// Lightweight flag wait: volatile L2 load poll (no atomic-RMW serialization).
__device__ __forceinline__ void wait_flag(const int* p, int target) {
    while (*(volatile const int*)p < target) __nanosleep(1024);
}

// ============================================================================
// Prologue: weight transpose+split (z = 4 weights); block (0,0,0) also zeroes
// the dataflow flags (kernel completes before mega_kernel starts).
// ============================================================================
struct TArg { const float* W[4]; __nv_bfloat16* Th[4]; __nv_bfloat16* Tl[4]; };

__global__ void __launch_bounds__(256)
transpose_split_kernel(TArg p)
{
    __shared__ float t[32][33];
    const int z = blockIdx.z;
    if (z == 0 && blockIdx.x == 0 && blockIdx.y == 0) {
        const int tid = threadIdx.y * 32 + threadIdx.x;
        if (tid < 3 * 8 * BSZ) ((int*)g_cntP)[tid] = 0;
        if (tid < BSZ * 16)    ((int*)g_cntA)[tid] = 0;
    }
    const float* W = p.W[z];
    __nv_bfloat16* Th = p.Th[z];
    __nv_bfloat16* Tl = p.Tl[z];
    const int tx = threadIdx.x, ty = threadIdx.y;       // 32 x 8
    const int nb = blockIdx.x * 32, kb = blockIdx.y * 32;
    #pragma unroll
    for (int i = 0; i < 4; i++)
        t[ty + i * 8][tx] = W[(size_t)(kb + ty + i * 8) * DIM + nb + tx];
    __syncthreads();
    #pragma unroll
    for (int i = 0; i < 4; i++) {
        const float v = t[tx][ty + i * 8];
        const __nv_bfloat16 h = __float2bfloat16(v);
        Th[(size_t)(nb + ty + i * 8) * DIM + kb + tx] = h;
        Tl[(size_t)(nb + ty + i * 8) * DIM + kb + tx] =
            __float2bfloat16(v - __bfloat162float(h));
    }
}

// ============================================================================
// GEMM body. CTA 128x128, 8 warps (4M x 2N), BK=32, 3-stage cp.async pipeline,
// XOR-swizzled bf16 tiles (64B rows, no padding).
// ============================================================================
#define GSTRIDE    36864
#define MEGA_SMEM  110592

struct GArg {
    const float* Af;
    const __nv_bfloat16 *Ah, *Al;
    const __nv_bfloat16 *Wh, *Wl;
    const float* bias;
    float* Cf;
    __nv_bfloat16 *Ch, *Cl;
    int omode;
    float scale;
};

template <int AFP32>
__device__ void gemm_body(const GArg& a, int bxx, int byy, char* smem)
{
    const uint32_t sb = smem_u32(smem);
    const int tid = threadIdx.x;
    const int wid = tid >> 5, lane = tid & 31;
    const int wm = wid & 3, wn = wid >> 2;
    const int m0 = byy * 128, n0 = bxx * 128;

    const int a_row  = lane & 15;
    const int a_c16  = (lane >> 4) & 1;
    const int b_nrow = (lane & 7) + ((lane >> 4) & 1) * 8;
    const int b_c16  = (lane >> 3) & 1;

    float acc[2][8][4];
    #pragma unroll
    for (int i = 0; i < 2; i++)
        #pragma unroll
        for (int j = 0; j < 8; j++)
            #pragma unroll
            for (int k = 0; k < 4; k++) acc[i][j][k] = 0.f;

    const int wOff = AFP32 ? 20480 : 16384;

    auto issue = [&](int it) {
        const int kc = it * 32;
        const uint32_t st = sb + (it % 3) * GSTRIDE;
        if (AFP32) {
            #pragma unroll
            for (int i = 0; i < 4; i++) {
                const int idx = tid + i * 256;
                const int r = idx >> 3, c = idx & 7;
                CP_ASYNC16(st + r * 160 + c * 16,
                           a.Af + (size_t)(m0 + r) * DIM + kc + c * 4);
            }
            #pragma unroll
            for (int i = 0; i < 2; i++) {
                const int idx = tid + i * 256;
                const int r = idx >> 2, c16 = idx & 3;
                const uint32_t o = SWZ(r, c16);
                const size_t gw = (size_t)(n0 + r) * DIM + kc + c16 * 8;
                CP_ASYNC16(st + 20480 + o, a.Wh + gw);
                CP_ASYNC16(st + 28672 + o, a.Wl + gw);
            }
        } else {
            #pragma unroll
            for (int i = 0; i < 2; i++) {
                const int idx = tid + i * 256;
                const int r = idx >> 2, c16 = idx & 3;
                const uint32_t o = SWZ(r, c16);
                const size_t ga = (size_t)(m0 + r) * DIM + kc + c16 * 8;
                const size_t gw = (size_t)(n0 + r) * DIM + kc + c16 * 8;
                CP_ASYNC16(st + o,         a.Ah + ga);
                CP_ASYNC16(st + 8192 + o,  a.Al + ga);
                CP_ASYNC16(st + 16384 + o, a.Wh + gw);
                CP_ASYNC16(st + 24576 + o, a.Wl + gw);
            }
        }
        CP_COMMIT();
    };

    issue(0);
    issue(1);

    #pragma unroll 1
    for (int it = 0; it < 32; ++it) {
        if (it + 1 < 32) { CP_WAIT(1); } else { CP_WAIT(0); }
        __syncthreads();
        if (it + 2 < 32) issue(it + 2);

        const uint32_t st = sb + (it % 3) * GSTRIDE;
        const char* stc = smem + (it % 3) * GSTRIDE;

        #pragma unroll
        for (int ks = 0; ks < 2; ++ks) {
            uint32_t ah[2][4], al[2][4];
            if (AFP32) {
                const int cb = ks * 16 + (lane & 3) * 2;
                #pragma unroll
                for (int mt = 0; mt < 2; ++mt) {
                    const int r = wm * 32 + mt * 16 + (lane >> 2);
                    const char* base = stc + (size_t)r * 160 + cb * 4;
                    const float2 v00 = *(const float2*)(base);
                    const float2 v01 = *(const float2*)(base + 8 * 160);
                    const float2 v10 = *(const float2*)(base + 32);
                    const float2 v11 = *(const float2*)(base + 8 * 160 + 32);
                    split2(v00, ah[mt][0], al[mt][0]);
                    split2(v01, ah[mt][1], al[mt][1]);
                    split2(v10, ah[mt][2], al[mt][2]);
                    split2(v11, ah[mt][3], al[mt][3]);
                }
            } else {
                #pragma unroll
                for (int mt = 0; mt < 2; ++mt) {
                    const int ar = wm * 32 + mt * 16 + a_row;
                    const uint32_t ao = SWZ(ar, ks * 2 + a_c16);
                    LDM_X4(ah[mt][0], ah[mt][1], ah[mt][2], ah[mt][3], st + ao);
                    LDM_X4(al[mt][0], al[mt][1], al[mt][2], al[mt][3], st + 8192 + ao);
                }
            }
            uint32_t b[4][4];
            #pragma unroll
            for (int g = 0; g < 4; ++g) {
                const int br = wn * 64 + g * 16 + b_nrow;
                LDM_X4(b[g][0], b[g][1], b[g][2], b[g][3],
                       st + wOff + SWZ(br, ks * 2 + b_c16));
            }
            #pragma unroll
            for (int mt = 0; mt < 2; ++mt)
                #pragma unroll
                for (int nt = 0; nt < 8; ++nt) {
                    MMA_BF16(acc[mt][nt], ah[mt],
                             b[nt >> 1][(nt & 1) * 2], b[nt >> 1][(nt & 1) * 2 + 1]);
                    MMA_BF16(acc[mt][nt], al[mt],
                             b[nt >> 1][(nt & 1) * 2], b[nt >> 1][(nt & 1) * 2 + 1]);
                }
            #pragma unroll
            for (int g = 0; g < 4; ++g) {
                const int br = wn * 64 + g * 16 + b_nrow;
                LDM_X4(b[g][0], b[g][1], b[g][2], b[g][3],
                       st + wOff + 8192 + SWZ(br, ks * 2 + b_c16));
            }
            #pragma unroll
            for (int mt = 0; mt < 2; ++mt)
                #pragma unroll
                for (int nt = 0; nt < 8; ++nt)
                    MMA_BF16(acc[mt][nt], ah[mt],
                             b[nt >> 1][(nt & 1) * 2], b[nt >> 1][(nt & 1) * 2 + 1]);
        }
    }

    // ---- epilogue
    const int r0l = lane >> 2, c0 = (lane & 3) * 2;
    #pragma unroll
    for (int mt = 0; mt < 2; ++mt) {
        #pragma unroll
        for (int nt = 0; nt < 8; ++nt) {
            const int n = n0 + wn * 64 + nt * 8 + c0;
            const float bx = a.bias[n], by = a.bias[n + 1];
            #pragma unroll
            for (int half = 0; half < 2; ++half) {
                const int r = m0 + wm * 32 + mt * 16 + r0l + half * 8;
                const float vx = (acc[mt][nt][half * 2 + 0] + bx) * a.scale;
                const float vy = (acc[mt][nt][half * 2 + 1] + by) * a.scale;
                if (a.omode == 2) {
                    *(float2*)&a.Cf[(size_t)r * DIM + n] = make_float2(vx, vy);
                } else {
                    const int bb = r >> 11, s = r & (SEQ - 1);
                    const int hh = n >> 6, d = n & (DH - 1);
                    const __nv_bfloat16 hx = __float2bfloat16(vx);
                    const __nv_bfloat16 hy = __float2bfloat16(vy);
                    const __nv_bfloat16 lx = __float2bfloat16(vx - __bfloat162float(hx));
                    const __nv_bfloat16 ly = __float2bfloat16(vy - __bfloat162float(hy));
                    if (a.omode == 0) {
                        const size_t idx = ((size_t)(bb * H + hh) * SEQ + s) * DH + d;
                        __nv_bfloat162 hv; hv.x = hx; hv.y = hy;
                        __nv_bfloat162 lv; lv.x = lx; lv.y = ly;
                        *(__nv_bfloat162*)(a.Ch + idx) = hv;
                        *(__nv_bfloat162*)(a.Cl + idx) = lv;
                    } else {
                        const size_t base = (size_t)(bb * H + hh) * DH;
                        a.Ch[(base + d) * SEQ + s]     = hx;
                        a.Ch[(base + d + 1) * SEQ + s] = hy;
                        a.Cl[(base + d) * SEQ + s]     = lx;
                        a.Cl[(base + d + 1) * SEQ + s] = ly;
                    }
                }
            }
        }
    }
}

// ============================================================================
// Attention body (R13-proven). 128 q-rows of one (b,h), 2-stage KV pipeline
// (pitch 144), Q persistent, max-free fused softmax, int32 mask direct reads.
// ============================================================================
#define ATTN_QH   73728
#define ATTN_QL   92160

__device__ void attn_body(const int32_t* __restrict__ mask,
        const __nv_bfloat16* __restrict__ qh, const __nv_bfloat16* __restrict__ ql,
        const __nv_bfloat16* __restrict__ kh, const __nv_bfloat16* __restrict__ kl,
        const __nv_bfloat16* __restrict__ vth, const __nv_bfloat16* __restrict__ vtl,
        __nv_bfloat16* __restrict__ oh, __nv_bfloat16* __restrict__ ol,
        int qt, int bh, char* smem)
{
    const uint32_t sb = smem_u32(smem);
    const int tid = threadIdx.x;
    const int wid = tid >> 5, lane = tid & 31;
    const int b = bh >> 4, h = bh & 15;
    const int q0 = qt * 128;
    const int wrow = wid * 16;

    const int a_row  = lane & 15;
    const int a_koff = ((lane >> 4) & 1) * 8;
    const int b_nrow = (lane & 7) + ((lane >> 4) & 1) * 8;
    const int b_koff = ((lane >> 3) & 1) * 8;
    const int r0 = lane >> 2, c2 = (lane & 3) * 2;

    #pragma unroll
    for (int i = 0; i < 8; i++) {
        const int idx = tid + i * 256;
        const int part = idx >> 10;
        const int id = idx & 1023;
        const int r = id >> 3, c = id & 7;
        const __nv_bfloat16* src = (part ? ql : qh)
            + ((size_t)bh * SEQ + q0 + r) * DH + c * 8;
        CP_ASYNC16(sb + (part ? ATTN_QL : ATTN_QH) + r * 144 + c * 16, src);
    }
    CP_COMMIT();

    float O[8][4];
    #pragma unroll
    for (int nt = 0; nt < 8; nt++)
        #pragma unroll
        for (int q = 0; q < 4; q++) O[nt][q] = 0.f;
    float lrun0 = 0.f, lrun1 = 0.f;

    const int row0 = q0 + wrow + r0;
    const int32_t* mp0 = mask + ((size_t)(b * SEQ + row0)) * ((size_t)H * SEQ)
                       + (size_t)h * SEQ;
    const int32_t* mp1 = mp0 + (size_t)8 * H * SEQ;

    auto issue_kv = [&](int kt) {
        const int k0i = kt * 64;
        const uint32_t st = sb + (kt & 1) * 36864;
        #pragma unroll
        for (int i = 0; i < 8; i++) {
            const int idx = tid + i * 256;
            const int part = idx >> 9;
            const int id = idx & 511;
            const int r = id >> 3, c = id & 7;
            const __nv_bfloat16* src;
            if (part == 0)      src = kh  + ((size_t)bh * SEQ + k0i + r) * DH + c * 8;
            else if (part == 1) src = kl  + ((size_t)bh * SEQ + k0i + r) * DH + c * 8;
            else if (part == 2) src = vth + ((size_t)bh * DH + r) * SEQ + k0i + c * 8;
            else                src = vtl + ((size_t)bh * DH + r) * SEQ + k0i + c * 8;
            CP_ASYNC16(st + part * 9216 + r * 144 + c * 16, src);
        }
        CP_COMMIT();
    };

    issue_kv(0);

    #pragma unroll 1
    for (int kt = 0; kt < 32; ++kt) {
        const int k0 = kt * 64;
        CP_WAIT(0);
        __syncthreads();
        if (kt + 1 < 32) issue_kv(kt + 1);

        const uint32_t kbase = sb + (kt & 1) * 36864;
        const uint32_t qho = sb + ATTN_QH + (wrow + a_row) * 144 + a_koff * 2;
        const uint32_t qlo = sb + ATTN_QL + (wrow + a_row) * 144 + a_koff * 2;

        float S[8][4];
        #pragma unroll
        for (int nt = 0; nt < 8; nt++)
            #pragma unroll
            for (int q = 0; q < 4; q++) S[nt][q] = 0.f;

        #pragma unroll
        for (int ks = 0; ks < 4; ++ks) {
            uint32_t qhf[4], qlf[4];
            LDM_X4(qhf[0], qhf[1], qhf[2], qhf[3], qho + ks * 32);
            LDM_X4(qlf[0], qlf[1], qlf[2], qlf[3], qlo + ks * 32);
            uint32_t bf[4][4];
            #pragma unroll
            for (int g = 0; g < 4; ++g)
                LDM_X4(bf[g][0], bf[g][1], bf[g][2], bf[g][3],
                       kbase + (g * 16 + b_nrow) * 144 + (ks * 16 + b_koff) * 2);
            #pragma unroll
            for (int nt = 0; nt < 8; ++nt) {
                MMA_BF16(S[nt], qhf, bf[nt >> 1][(nt & 1) * 2], bf[nt >> 1][(nt & 1) * 2 + 1]);
                MMA_BF16(S[nt], qlf, bf[nt >> 1][(nt & 1) * 2], bf[nt >> 1][(nt & 1) * 2 + 1]);
            }
            #pragma unroll
            for (int g = 0; g < 4; ++g)
                LDM_X4(bf[g][0], bf[g][1], bf[g][2], bf[g][3],
                       kbase + 9216 + (g * 16 + b_nrow) * 144 + (ks * 16 + b_koff) * 2);
            #pragma unroll
            for (int nt = 0; nt < 8; ++nt)
                MMA_BF16(S[nt], qhf, bf[nt >> 1][(nt & 1) * 2], bf[nt >> 1][(nt & 1) * 2 + 1]);
        }

        const uint32_t vtb = kbase + 18432;
        #pragma unroll
        for (int ks = 0; ks < 4; ++ks) {
            uint32_t ph[4], pl[4];
            #pragma unroll
            for (int hf = 0; hf < 2; ++hf) {
                const int nt = 2 * ks + hf;
                const int coff = k0 + nt * 8 + c2;
                const int2 m0 = *(const int2*)(mp0 + coff);
                const int2 m1 = *(const int2*)(mp1 + coff);
                float p;
                EX2F(p, S[nt][0]); if (m0.x) p = 0.f; S[nt][0] = p; lrun0 += p;
                EX2F(p, S[nt][1]); if (m0.y) p = 0.f; S[nt][1] = p; lrun0 += p;
                EX2F(p, S[nt][2]); if (m1.x) p = 0.f; S[nt][2] = p; lrun1 += p;
                EX2F(p, S[nt][3]); if (m1.y) p = 0.f; S[nt][3] = p; lrun1 += p;

                __nv_bfloat162 h01, h23, l01, l23;
                h01.x = __float2bfloat16(S[nt][0]);
                h01.y = __float2bfloat16(S[nt][1]);
                h23.x = __float2bfloat16(S[nt][2]);
                h23.y = __float2bfloat16(S[nt][3]);
                l01.x = __float2bfloat16(S[nt][0] - __bfloat162float(h01.x));
                l01.y = __float2bfloat16(S[nt][1] - __bfloat162float(h01.y));
                l23.x = __float2bfloat16(S[nt][2] - __bfloat162float(h23.x));
                l23.y = __float2bfloat16(S[nt][3] - __bfloat162float(h23.y));
                ph[hf * 2 + 0] = *(uint32_t*)&h01;
                ph[hf * 2 + 1] = *(uint32_t*)&h23;
                pl[hf * 2 + 0] = *(uint32_t*)&l01;
                pl[hf * 2 + 1] = *(uint32_t*)&l23;
            }
            uint32_t bf[4][4];
            #pragma unroll
            for (int g = 0; g < 4; ++g)
                LDM_X4(bf[g][0], bf[g][1], bf[g][2], bf[g][3],
                       vtb + (g * 16 + b_nrow) * 144 + (ks * 16 + b_koff) * 2);
            #pragma unroll
            for (int nt = 0; nt < 8; ++nt) {
                MMA_BF16(O[nt], ph, bf[nt >> 1][(nt & 1) * 2], bf[nt >> 1][(nt & 1) * 2 + 1]);
                MMA_BF16(O[nt], pl, bf[nt >> 1][(nt & 1) * 2], bf[nt >> 1][(nt & 1) * 2 + 1]);
            }
            #pragma unroll
            for (int g = 0; g < 4; ++g)
                LDM_X4(bf[g][0], bf[g][1], bf[g][2], bf[g][3],
                       vtb + 9216 + (g * 16 + b_nrow) * 144 + (ks * 16 + b_koff) * 2);
            #pragma unroll
            for (int nt = 0; nt < 8; ++nt)
                MMA_BF16(O[nt], ph, bf[nt >> 1][(nt & 1) * 2], bf[nt >> 1][(nt & 1) * 2 + 1]);
        }
    }

    lrun0 += __shfl_xor_sync(0xffffffffu, lrun0, 1);
    lrun0 += __shfl_xor_sync(0xffffffffu, lrun0, 2);
    lrun1 += __shfl_xor_sync(0xffffffffu, lrun1, 1);
    lrun1 += __shfl_xor_sync(0xffffffffu, lrun1, 2);

    const float inv0 = __fdividef(1.f, lrun0);
    const float inv1 = __fdividef(1.f, lrun1);
    #pragma unroll
    for (int nt = 0; nt < 8; ++nt) {
        const int d = h * DH + nt * 8 + c2;
        {
            const float v0 = O[nt][0] * inv0, v1 = O[nt][1] * inv0;
            const size_t idx = ((size_t)(b * SEQ) + row0) * DIM + d;
            __nv_bfloat162 hv, lv;
            hv.x = __float2bfloat16(v0); hv.y = __float2bfloat16(v1);
            lv.x = __float2bfloat16(v0 - __bfloat162float(hv.x));
            lv.y = __float2bfloat16(v1 - __bfloat162float(hv.y));
            *(__nv_bfloat162*)(oh + idx) = hv;
            *(__nv_bfloat162*)(ol + idx) = lv;
        }
        {
            const float v0 = O[nt][2] * inv1, v1 = O[nt][3] * inv1;
            const size_t idx = ((size_t)(b * SEQ) + row0 + 8) * DIM + d;
            __nv_bfloat162 hv, lv;
            hv.x = __float2bfloat16(v0); hv.y = __float2bfloat16(v1);
            lv.x = __float2bfloat16(v0 - __bfloat162float(hv.x));
            lv.y = __float2bfloat16(v1 - __bfloat162float(hv.y));
            *(__nv_bfloat162*)(oh + idx) = hv;
            *(__nv_bfloat162*)(ol + idx) = lv;
        }
    }
}

// ============================================================================
// Mega kernel: CTAs [0,1536) projections (z fastest), [1536,2560) attention,
// [2560,3072) output GEMM. Flag-based dataflow (volatile-poll waits).
// ============================================================================
struct MParams {
    const float *query, *key, *value;
    const int32_t* mask;
    const float *bq, *bk, *bv, *bo;
    const __nv_bfloat16 *wh, *wl;
    __nv_bfloat16 *qh, *ql, *kh, *kl, *vth, *vtl, *oh, *ol;
    float* out;
};

__global__ void __launch_bounds__(256, 2)
mega_kernel(MParams p)
{
    extern __shared__ __align__(128) char smem[];
    const int bx = blockIdx.x;
    const int tid = threadIdx.x;
    const size_t WD = (size_t)DIM * DIM;

    if (bx < 1536) {
        const int z = bx % 3;
        const int r = bx / 3;
        const int xn = r & 7;
        const int ym = r >> 3;
        GArg a;
        if (z == 0)      a = { p.query, nullptr, nullptr, p.wh + 0 * WD, p.wl + 0 * WD,
                               p.bq, nullptr, p.qh, p.ql, 0, QSCALE };
        else if (z == 1) a = { p.key,   nullptr, nullptr, p.wh + 1 * WD, p.wl + 1 * WD,
                               p.bk, nullptr, p.kh, p.kl, 0, 1.0f };
        else             a = { p.value, nullptr, nullptr, p.wh + 2 * WD, p.wl + 2 * WD,
                               p.bv, nullptr, p.vth, p.vtl, 1, 1.0f };
        gemm_body<1>(a, xn, ym, smem);
        __threadfence();
        __syncthreads();
        if (tid == 0) atomicAdd(&g_cntP[z][xn][ym >> 4], 1);
    } else if (bx < 2560) {
        const int aidx = bx - 1536;
        const int h = aidx & 15;
        const int qt = (aidx >> 4) & 15;
        const int b = aidx >> 8;
        if (tid == 0) {
            const int nt = h >> 1;
            wait_flag(&g_cntP[0][nt][b], 16);
            wait_flag(&g_cntP[1][nt][b], 16);
            wait_flag(&g_cntP[2][nt][b], 16);
        }
        __syncthreads();
        __threadfence();
        attn_body(p.mask, p.qh, p.ql, p.kh, p.kl, p.vth, p.vtl, p.oh, p.ol,
                  qt, b * 16 + h, smem);
        __threadfence();
        __syncthreads();
        if (tid == 0) atomicAdd(&g_cntA[b][qt], 1);
    } else {
        const int oidx = bx - 2560;
        const int xn = oidx & 7;
        const int ym = oidx >> 3;
        if (tid == 0)
            wait_flag(&g_cntA[ym >> 4][ym & 15], 16);
        __syncthreads();
        __threadfence();
        GArg a = { nullptr, p.oh, p.ol, p.wh + 3 * WD, p.wl + 3 * WD,
                   p.bo, p.out, nullptr, nullptr, 2, 1.0f };
        gemm_body<0>(a, xn, ym, smem);
    }
}

// ============================================================================
extern "C" void kernel_launch(void* const* d_in, const int* in_sizes, int n_in,
                              void* d_out, int out_size)
{
    const float* query = (const float*)d_in[0];
    const float* key_  = (const float*)d_in[1];
    const float* value = (const float*)d_in[2];
    const int32_t* mask = (const int32_t*)d_in[3];
    const float* Wq = (const float*)d_in[4];
    const float* bq = (const float*)d_in[5];
    const float* Wk = (const float*)d_in[6];
    const float* bk = (const float*)d_in[7];
    const float* Wv = (const float*)d_in[8];
    const float* bv = (const float*)d_in[9];
    const float* Wo = (const float*)d_in[10];
    const float* bo = (const float*)d_in[11];
    float* out = (float*)d_out;

    __nv_bfloat16 *wh, *wl, *qh, *ql, *kh, *kl, *vth, *vtl, *oh, *ol;
    cudaGetSymbolAddress((void**)&wh, g_wh);
    cudaGetSymbolAddress((void**)&wl, g_wl);
    cudaGetSymbolAddress((void**)&qh, g_qh);
    cudaGetSymbolAddress((void**)&ql, g_ql);
    cudaGetSymbolAddress((void**)&kh, g_kh);
    cudaGetSymbolAddress((void**)&kl, g_kl);
    cudaGetSymbolAddress((void**)&vth, g_vth);
    cudaGetSymbolAddress((void**)&vtl, g_vtl);
    cudaGetSymbolAddress((void**)&oh, g_oh);
    cudaGetSymbolAddress((void**)&ol, g_ol);
    const size_t WD = (size_t)DIM * DIM;

    cudaFuncSetAttribute(mega_kernel, cudaFuncAttributeMaxDynamicSharedMemorySize, MEGA_SMEM);

    // weight transpose+split + flag zeroing (one launch)
    TArg ta;
    ta.W[0] = Wq; ta.W[1] = Wk; ta.W[2] = Wv; ta.W[3] = Wo;
    for (int i = 0; i < 4; i++) { ta.Th[i] = wh + i * WD; ta.Tl[i] = wl + i * WD; }
    transpose_split_kernel<<<dim3(32, 32, 4), dim3(32, 8)>>>(ta);

    // fused projections + attention + output projection
    MParams mp;
    mp.query = query; mp.key = key_; mp.value = value; mp.mask = mask;
    mp.bq = bq; mp.bk = bk; mp.bv = bv; mp.bo = bo;
    mp.wh = wh; mp.wl = wl;
    mp.qh = qh; mp.ql = ql; mp.kh = kh; mp.kl = kl;
    mp.vth = vth; mp.vtl = vtl; mp.oh = oh; mp.ol = ol;
    mp.out = out;
    mega_kernel<<<3072, 256, MEGA_SMEM>>>(mp);
}